// round 10
// baseline (speedup 1.0000x reference)
#include <cuda_runtime.h>
#include <cuda_fp16.h>
#include <cstddef>

#define NB 2
#define NC 128
#define TWOC 256
#define NE 60000
#define TR_BLOCKS (2 * NB * 2 * (NE / 32))          // 15000 transpose tiles
#define W_WARPS   (2 * NC * 15 + 3)
#define W_BLOCKS  ((W_WARPS + 7) / 8)
#define GROUPS4   (NB * NE / 4)                      // 30000 4-edge groups

// Transposed inputs in fp16, tensor-interleaved: [b][e][tensor][c]
__device__ __half g_xti[(size_t)NB * NE * TWOC];
// Effective fused weights: [branch][c][s*3+k] padded to 16
__device__ float g_V[2][NC][16];
__device__ float g_cb[3];

// ---------------------------------------------------------------------------
// Kernel 1 (fused): transpose tiles + weight folding + output zeroing.
// ---------------------------------------------------------------------------
__global__ void __launch_bounds__(256)
prep_kernel(const float* __restrict__ x0, const float* __restrict__ x1,
    const float* __restrict__ Wa_local, const float* __restrict__ ba_local,
    const float* __restrict__ Wb_local, const float* __restrict__ bb_local,
    const float* __restrict__ Wa_tri,   const float* __restrict__ ba_tri,
    const float* __restrict__ Wb_tri,   const float* __restrict__ bb_tri,
    const float* __restrict__ Wa_fuse,  const float* __restrict__ ba_fuse,
    const float* __restrict__ Wb_fuse,  const float* __restrict__ bb_fuse,
    float* __restrict__ out, int out_n)
{
    if (blockIdx.x < TR_BLOCKS) {
        __shared__ __half tile[32][66];   // [e_local][c_local], stride 66 halves
        int bx = blockIdx.x;
        const int eb = bx % (NE / 32);  bx /= (NE / 32);
        const int ch = bx & 1;          bx >>= 1;
        const int b  = bx & 1;
        const int tensor = bx >> 1;
        const float* __restrict__ src = tensor ? x1 : x0;
        const int e0 = eb * 32, c0 = ch * 64;
        const int tx = threadIdx.x & 31;
        const int ty = threadIdx.x >> 5;

#pragma unroll
        for (int i = 0; i < 8; i++) {
            int cl = ty + 8 * i;
            tile[tx][cl] = __float2half_rn(
                src[((size_t)b * NC + c0 + cl) * NE + e0 + tx]);
        }
        __syncthreads();
#pragma unroll
        for (int it = 0; it < 4; it++) {
            int e = ty * 4 + it;
            unsigned v = *reinterpret_cast<const unsigned*>(&tile[e][2 * tx]);
            *reinterpret_cast<unsigned*>(
                g_xti + ((size_t)(b * NE + e0 + e)) * TWOC
                      + tensor * NC + c0 + 2 * tx) = v;
        }
        return;
    }

    if (blockIdx.x >= TR_BLOCKS + W_BLOCKS) {
        // ---- output zeroing (float4) ----
        int i = (blockIdx.x - TR_BLOCKS - W_BLOCKS) * 256 + threadIdx.x;
        int n4 = out_n >> 2;
        if (i < n4)
            reinterpret_cast<float4*>(out)[i] = make_float4(0.f, 0.f, 0.f, 0.f);
        if (i == 0)
            for (int r = n4 * 4; r < out_n; r++) out[r] = 0.f;
        return;
    }

    // ---- weight folding: one warp per output ----
    const int lane = threadIdx.x & 31;
    const int w = (blockIdx.x - TR_BLOCKS) * 8 + (threadIdx.x >> 5);

    if (w < 2 * NC * 15) {
        const int t   = w / (NC * 15);
        const int rem = w - t * (NC * 15);
        const int c   = rem / 15;
        const int sk  = rem - c * 15;
        const int s   = sk / 3;
        const int k   = sk - s * 3;
        const float* Wf = t ? Wb_fuse  : Wa_fuse;
        const float* Wt = t ? Wb_tri   : Wa_tri;
        const float* Wl = t ? Wb_local : Wa_local;
        float acc = 0.f;
#pragma unroll
        for (int j = 0; j < 4; j++) {
            int o = lane + 32 * j;
            acc = fmaf(Wf[k * (2 * NC) + NC + o], Wt[(o * NC + c) * 5 + s], acc);
            if (s == 0)
                acc = fmaf(Wf[k * (2 * NC) + o], Wl[o * NC + c], acc);
        }
#pragma unroll
        for (int off = 16; off; off >>= 1)
            acc += __shfl_xor_sync(0xffffffffu, acc, off);
        if (lane == 0) {
            g_V[t][c][sk] = acc;
            if (sk == 0) g_V[t][c][15] = 0.f;
        }
    } else if (w < 2 * NC * 15 + 3) {
        const int k = w - 2 * NC * 15;
        float acc = 0.f;
#pragma unroll
        for (int j = 0; j < 4; j++) {
            int o = lane + 32 * j;
            acc = fmaf(Wa_fuse[k * 2 * NC + o],      ba_local[o], acc);
            acc = fmaf(Wa_fuse[k * 2 * NC + NC + o], ba_tri[o],   acc);
            acc = fmaf(Wb_fuse[k * 2 * NC + o],      bb_local[o], acc);
            acc = fmaf(Wb_fuse[k * 2 * NC + NC + o], bb_tri[o],   acc);
        }
#pragma unroll
        for (int off = 16; off; off >>= 1)
            acc += __shfl_xor_sync(0xffffffffu, acc, off);
        if (lane == 0)
            g_cb[k] = acc + ba_fuse[k] + bb_fuse[k];
    }
}

// ---------------------------------------------------------------------------
// Kernel 2: main gather + fused dot. EACH WARP owns ONE TENSOR of a 4-edge
// group (warp pairs share the group). Lane owns 4 channels of its tensor:
// 30 weight regs -> 24 warps/SM. Partials combined via RED.ADD.F32 to gmem
// (2 deterministic contributors per element; out pre-zeroed by prep).
// ---------------------------------------------------------------------------
__device__ __forceinline__ __half2 u2h(const unsigned& u)
{
    return *reinterpret_cast<const __half2*>(&u);
}

// one edge, one tensor (4 channels = 2 half2 slots) -> res[0..2]
__device__ __forceinline__ void edge_dot(
    const uint2 r0, const uint2 r1, const uint2 r2,
    const uint2 r3, const uint2 r4,
    const __half2 Vp[2][15], float* __restrict__ res)
{
    __half2 n1a = u2h(r1.x), n1b = u2h(r1.y);
    __half2 n2a = u2h(r2.x), n2b = u2h(r2.y);
    __half2 n3a = u2h(r3.x), n3b = u2h(r3.y);
    __half2 n4a = u2h(r4.x), n4b = u2h(r4.y);

    __half2 Ga[5], Gb[5];
    Ga[0] = u2h(r0.x);
    Gb[0] = u2h(r0.y);
    Ga[1] = __hadd2(n1a, n3a);  Gb[1] = __hadd2(n1b, n3b);
    Ga[2] = __hadd2(n2a, n4a);  Gb[2] = __hadd2(n2b, n4b);
    Ga[3] = __habs2(__hsub2(n1a, n3a));  Gb[3] = __habs2(__hsub2(n1b, n3b));
    Ga[4] = __habs2(__hsub2(n2a, n4a));  Gb[4] = __habs2(__hsub2(n2b, n4b));

    __half2 A0 = __hmul2(Vp[0][0], Ga[0]);
    __half2 A1 = __hmul2(Vp[0][1], Ga[0]);
    __half2 A2 = __hmul2(Vp[0][2], Ga[0]);
    __half2 B0 = __hmul2(Vp[1][0], Gb[0]);
    __half2 B1 = __hmul2(Vp[1][1], Gb[0]);
    __half2 B2 = __hmul2(Vp[1][2], Gb[0]);
#pragma unroll
    for (int s = 1; s < 5; s++) {
        A0 = __hfma2(Vp[0][s * 3 + 0], Ga[s], A0);
        A1 = __hfma2(Vp[0][s * 3 + 1], Ga[s], A1);
        A2 = __hfma2(Vp[0][s * 3 + 2], Ga[s], A2);
        B0 = __hfma2(Vp[1][s * 3 + 0], Gb[s], B0);
        B1 = __hfma2(Vp[1][s * 3 + 1], Gb[s], B1);
        B2 = __hfma2(Vp[1][s * 3 + 2], Gb[s], B2);
    }
    float2 a0 = __half22float2(A0), b0 = __half22float2(B0);
    float2 a1 = __half22float2(A1), b1 = __half22float2(B1);
    float2 a2 = __half22float2(A2), b2 = __half22float2(B2);
    res[0] = (a0.x + a0.y) + (b0.x + b0.y);
    res[1] = (a1.x + a1.y) + (b1.x + b1.y);
    res[2] = (a2.x + a2.y) + (b2.x + b2.y);
}

// one PAIR of edges for this tensor: 10 batched LDG.64 -> res[0..5]
__device__ __forceinline__ void do_pair(
    const __half* __restrict__ base,
    int e, const int4 gi0, const int4 gi1,
    const __half2 Vp[2][15], float* __restrict__ res)
{
    uint2 a0 = *reinterpret_cast<const uint2*>(base + (size_t)e     * TWOC);
    uint2 a1 = *reinterpret_cast<const uint2*>(base + (size_t)gi0.x * TWOC);
    uint2 a2 = *reinterpret_cast<const uint2*>(base + (size_t)gi0.y * TWOC);
    uint2 a3 = *reinterpret_cast<const uint2*>(base + (size_t)gi0.z * TWOC);
    uint2 a4 = *reinterpret_cast<const uint2*>(base + (size_t)gi0.w * TWOC);
    uint2 c0 = *reinterpret_cast<const uint2*>(base + (size_t)(e+1) * TWOC);
    uint2 c1 = *reinterpret_cast<const uint2*>(base + (size_t)gi1.x * TWOC);
    uint2 c2 = *reinterpret_cast<const uint2*>(base + (size_t)gi1.y * TWOC);
    uint2 c3 = *reinterpret_cast<const uint2*>(base + (size_t)gi1.z * TWOC);
    uint2 c4 = *reinterpret_cast<const uint2*>(base + (size_t)gi1.w * TWOC);

    edge_dot(a0, a1, a2, a3, a4, Vp, res);
    edge_dot(c0, c1, c2, c3, c4, Vp, res + 3);
}

__global__ void __launch_bounds__(256, 3)
mesh_main_kernel(const int* __restrict__ gemm, float* __restrict__ out)
{
    const int lane = threadIdx.x & 31;
    const int W    = blockIdx.x * 8 + (threadIdx.x >> 5);
    const int t    = W & 1;                 // tensor this warp owns
    const int g0   = W >> 1;                // 4-edge group index
    const int GS   = (gridDim.x * 8) >> 1;  // group stride

    // own-tensor weights for lane's 4 channels: 30 regs
    __half2 Vp[2][15];
#pragma unroll
    for (int j = 0; j < 2; j++) {
        const float* r0 = g_V[t][4 * lane + 2 * j];
        const float* r1 = g_V[t][4 * lane + 2 * j + 1];
#pragma unroll
        for (int sk = 0; sk < 15; sk++)
            Vp[j][sk] = __floats2half2_rn(r0[sk], r1[sk]);
    }
    // bias folded into tensor-0 warp's contribution
    float cbk = (t == 0 && lane < 12) ? g_cb[lane % 3] : 0.f;

    const int4* __restrict__ gi4 = reinterpret_cast<const int4*>(gemm);

    for (int g = g0; g < GROUPS4; g += GS) {
        const int e0 = 4 * g;
        const int b  = (e0 >= NE) ? 1 : 0;
        const int eb = e0 - b * NE;

        const int4 gA = gi4[(size_t)b * NE + eb];
        const int4 gB = gi4[(size_t)b * NE + eb + 1];
        const int4 gC = gi4[(size_t)b * NE + eb + 2];
        const int4 gD = gi4[(size_t)b * NE + eb + 3];

        const __half* __restrict__ base =
            g_xti + (size_t)b * NE * TWOC + t * NC + lane * 4;

        float res[12];
        do_pair(base, eb,     gA, gB, Vp, res);
        do_pair(base, eb + 2, gC, gD, Vp, res + 6);

        // deferred butterfly: 12 parallel chains x 5 rounds
#pragma unroll
        for (int off = 16; off; off >>= 1)
#pragma unroll
            for (int r = 0; r < 12; r++)
                res[r] += __shfl_xor_sync(0xffffffffu, res[r], off);

        if (lane < 12) {
            const int u = lane / 3;
            const int k = lane - 3 * u;
            atomicAdd(out + ((size_t)b * 3 + k) * NE + eb + u, res[lane] + cbk);
        }
    }
}

// ---------------------------------------------------------------------------
extern "C" void kernel_launch(void* const* d_in, const int* in_sizes, int n_in,
                              void* d_out, int out_size)
{
    const float* x_0      = (const float*)d_in[0];
    const float* x_1      = (const float*)d_in[1];
    const int*   gemm     = (const int*)  d_in[2];
    const float* Wa_local = (const float*)d_in[3];
    const float* ba_local = (const float*)d_in[4];
    const float* Wb_local = (const float*)d_in[5];
    const float* bb_local = (const float*)d_in[6];
    const float* Wa_tri   = (const float*)d_in[7];
    const float* ba_tri   = (const float*)d_in[8];
    const float* Wb_tri   = (const float*)d_in[9];
    const float* bb_tri   = (const float*)d_in[10];
    const float* Wa_fuse  = (const float*)d_in[11];
    const float* ba_fuse  = (const float*)d_in[12];
    const float* Wb_fuse  = (const float*)d_in[13];
    const float* bb_fuse  = (const float*)d_in[14];
    float* out = (float*)d_out;

    const int z_blocks = (out_size / 4 + 255) / 256 + 1;
    prep_kernel<<<TR_BLOCKS + W_BLOCKS + z_blocks, 256>>>(
        x_0, x_1,
        Wa_local, ba_local, Wb_local, bb_local,
        Wa_tri, ba_tri, Wb_tri, bb_tri,
        Wa_fuse, ba_fuse, Wb_fuse, bb_fuse,
        out, out_size);

    mesh_main_kernel<<<444, 256>>>(gemm, out);
}